// round 16
// baseline (speedup 1.0000x reference)
#include <cuda_runtime.h>
#include <cstdint>

// Problem constants (fixed by the dataset)
#define NMAX 100000
#define EMAX 800000
#define DD   96

// ---------------- device scratch (no runtime allocation allowed) -------------
// g_cnt is zero at module load and re-zeroed by the tail kernel at the end of
// every kernel_launch call, so each call starts from the same state.
__device__ int   g_cnt[NMAX];
__device__ int   g_src[EMAX];
__device__ int   g_dst[EMAX];
__device__ int   g_pos[EMAX];            // slot of edge within its src row
__device__ int   g_rowptr[NMAX + 1];
__device__ int   g_dst_sorted[EMAX];
__device__ float g_h[NMAX * DD];         // post-GEMM features
__device__ float g_y1[NMAX * DD];        // layer-1 output
__device__ float g_as[NMAX];
__device__ float g_ad[NMAX];

// ---------------- 1) convert + count (per-block dtype detect) ---------------
// src begins with arange(N): int32 view of int64 data = [0,0,1,0,2,0,...]
// (odd indices are zero high-words); int32 data = [0,1,2,...].
__global__ void convert_count_kernel(const void* __restrict__ eidx, int E) {
    __shared__ int s_flag;
    const int* p32 = (const int*)eidx;
    if (threadIdx.x == 0) {
        s_flag = ((p32[1] | p32[3] | p32[5] | p32[7] | p32[9]) == 0) ? 1 : 0;
    }
    __syncthreads();
    int e = blockIdx.x * blockDim.x + threadIdx.x;
    if (e >= E) return;
    int s, d;
    if (s_flag) {
        const long long* q = (const long long*)eidx;
        s = (int)q[e];
        d = (int)q[E + e];
    } else {
        s = p32[e];
        d = p32[E + e];
    }
    g_src[e] = s;
    g_dst[e] = d;
    g_pos[e] = atomicAdd(&g_cnt[s], 1);
}

// ---------------- 2) rowptr: single-block exclusive scan of counts ----------
__global__ void __launch_bounds__(1024) rowptr_kernel(int n) {
    __shared__ int s_w[32];
    __shared__ int s_tot;
    int t = threadIdx.x;
    int lane = t & 31;
    int wid = t >> 5;
    int carry = 0;

    for (int chunk = 0; chunk < n; chunk += 1024) {
        int i = chunk + t;
        int v = (i < n) ? g_cnt[i] : 0;
        // warp inclusive scan
        int x = v;
#pragma unroll
        for (int off = 1; off < 32; off <<= 1) {
            int y = __shfl_up_sync(0xffffffffu, x, off);
            if (lane >= off) x += y;
        }
        if (lane == 31) s_w[wid] = x;
        __syncthreads();
        if (t < 32) {
            int wv = s_w[t];
            int win = wv;
#pragma unroll
            for (int off = 1; off < 32; off <<= 1) {
                int y = __shfl_up_sync(0xffffffffu, win, off);
                if (t >= off) win += y;
            }
            if (t == 31) s_tot = win;
            s_w[t] = win - wv;         // exclusive warp offset
        }
        __syncthreads();
        int excl = carry + s_w[wid] + (x - v);
        if (i < n) g_rowptr[i] = excl;
        carry += s_tot;
        __syncthreads();               // protect s_w/s_tot before next chunk
    }
    if (t == 0) g_rowptr[n] = carry;
}

// ---------------- 3/5) mega: GEMM+dots OR atomic-free fill ------------------
// Blocks [0, gemmBlocks): H[n,96] = X @ W, plus as/ad dots fused.
// Blocks [gemmBlocks, ...): dst_sorted[rowptr[src]+pos] = dst (E=0 disables).
__global__ void __launch_bounds__(256) mega_gemm_fill_kernel(
    const float* __restrict__ X, const float* __restrict__ W,
    const float* __restrict__ A, float* __restrict__ H,
    int n, int E, int gemmBlocks)
{
    __shared__ float Ws[32 * 96];     // [k][j]
    __shared__ float Xs[64 * 33];     // [row][k], padded stride 33

    if (blockIdx.x >= gemmBlocks) {
        int e = (blockIdx.x - gemmBlocks) * 256 + threadIdx.x;
        if (e < E) {
            int s = g_src[e];
            g_dst_sorted[g_rowptr[s] + g_pos[e]] = g_dst[e];
        }
        return;
    }

    int tid = threadIdx.x;
    int lane = tid & 31;
    int ct = tid & 15;                // column group: cols [ct*6, ct*6+6)
    int rt = tid >> 4;                // row group: rows rt*4 .. rt*4+3
    int rowBase = blockIdx.x * 64;

    float acc[4][6];
#pragma unroll
    for (int i = 0; i < 4; ++i)
#pragma unroll
        for (int j = 0; j < 6; ++j) acc[i][j] = 0.f;

    for (int kc = 0; kc < 96; kc += 32) {
#pragma unroll
        for (int i = 0; i < 12; ++i) {
            int idx = tid + i * 256;
            Ws[idx] = W[kc * 96 + idx];
        }
#pragma unroll
        for (int i = 0; i < 8; ++i) {
            int idx = tid + i * 256;
            int r = idx >> 5, k = idx & 31;
            int grow = rowBase + r;
            Xs[r * 33 + k] = (grow < n) ? X[grow * 96 + kc + k] : 0.f;
        }
        __syncthreads();

#pragma unroll
        for (int k = 0; k < 32; ++k) {
            float xr[4];
#pragma unroll
            for (int i = 0; i < 4; ++i) xr[i] = Xs[(rt * 4 + i) * 33 + k];
            const float2* wp = (const float2*)&Ws[k * 96 + ct * 6];
            float2 w01 = wp[0], w23 = wp[1], w45 = wp[2];
            float wr[6] = {w01.x, w01.y, w23.x, w23.y, w45.x, w45.y};
#pragma unroll
            for (int i = 0; i < 4; ++i)
#pragma unroll
                for (int j = 0; j < 6; ++j) acc[i][j] += xr[i] * wr[j];
        }
        __syncthreads();
    }

#pragma unroll
    for (int i = 0; i < 4; ++i) {
        int grow = rowBase + rt * 4 + i;
        if (grow < n) {
#pragma unroll
            for (int j = 0; j < 6; ++j)
                H[grow * 96 + ct * 6 + j] = acc[i][j];
        }
    }

    // fused dots: per-row s = h.a[0:96], t = h.a[96:192]
    float aj[6], bj[6];
#pragma unroll
    for (int j = 0; j < 6; ++j) {
        aj[j] = A[ct * 6 + j];
        bj[j] = A[96 + ct * 6 + j];
    }
#pragma unroll
    for (int i = 0; i < 4; ++i) {
        float s = 0.f, t2 = 0.f;
#pragma unroll
        for (int j = 0; j < 6; ++j) {
            s  += acc[i][j] * aj[j];
            t2 += acc[i][j] * bj[j];
        }
#pragma unroll
        for (int off = 8; off > 0; off >>= 1) {
            s  += __shfl_xor_sync(0xffffffffu, s,  off);
            t2 += __shfl_xor_sync(0xffffffffu, t2, off);
        }
        int grow = rowBase + rt * 4 + i;
        if ((lane & 15) == 0 && grow < n) {
            g_as[grow] = s;
            g_ad[grow] = t2;
        }
    }
}

// ---------------- 4/6) gather v3 --------------------------------------------
// out[i] = sum_e w_e * h[dst_e] / sum_e w_e ; one warp per node.
// Chunk-prefetch up to 32 dst indices with ONE coalesced load, broadcast via
// shfl, then issue 4 edges' (ad + 3 row) loads fully independently.
// __launch_bounds__(256, 4): allow up to 64 regs so the loads stay in flight
// (R15's 32-reg cap serialized them -> issue 2.2%).
__device__ __forceinline__ float edge_w(float s) {
    // leaky_relu(s) == fmaxf(s, 0.01*s) for both signs
    return __expf(-fmaxf(s, 0.01f * s));
}

__global__ void __launch_bounds__(256, 4) gather_kernel(
    const float* __restrict__ h, float* __restrict__ out,
    int n, int do_relu)
{
    int warp = (blockIdx.x * blockDim.x + threadIdx.x) >> 5;
    int lane = threadIdx.x & 31;
    if (warp >= n) return;

    int p   = g_rowptr[warp];
    int end = g_rowptr[warp + 1];
    float asi = g_as[warp];

    float a0 = 0.f, a1 = 0.f, a2 = 0.f, rs = 0.f;

    while (p < end) {
        int m = end - p;
        if (m > 32) m = 32;
        // one coalesced load fetches this chunk's indices for the whole warp
        int dl = (lane < m) ? g_dst_sorted[p + lane] : 0;

        int j = 0;
        for (; j + 4 <= m; j += 4) {
            int d0 = __shfl_sync(0xffffffffu, dl, j);
            int d1 = __shfl_sync(0xffffffffu, dl, j + 1);
            int d2 = __shfl_sync(0xffffffffu, dl, j + 2);
            int d3 = __shfl_sync(0xffffffffu, dl, j + 3);
            // 4 ad loads + 12 row loads, all independent
            float s0 = g_ad[d0], s1 = g_ad[d1], s2 = g_ad[d2], s3 = g_ad[d3];
            const float* r0 = h + d0 * 96;
            const float* r1 = h + d1 * 96;
            const float* r2 = h + d2 * 96;
            const float* r3 = h + d3 * 96;
            float x00 = r0[lane], x01 = r0[lane + 32], x02 = r0[lane + 64];
            float x10 = r1[lane], x11 = r1[lane + 32], x12 = r1[lane + 64];
            float x20 = r2[lane], x21 = r2[lane + 32], x22 = r2[lane + 64];
            float x30 = r3[lane], x31 = r3[lane + 32], x32 = r3[lane + 64];
            float w0 = edge_w(asi + s0);
            float w1 = edge_w(asi + s1);
            float w2 = edge_w(asi + s2);
            float w3 = edge_w(asi + s3);
            rs += (w0 + w1) + (w2 + w3);
            a0 += w0 * x00 + w1 * x10 + w2 * x20 + w3 * x30;
            a1 += w0 * x01 + w1 * x11 + w2 * x21 + w3 * x31;
            a2 += w0 * x02 + w1 * x12 + w2 * x22 + w3 * x32;
        }
        for (; j < m; ++j) {
            int d = __shfl_sync(0xffffffffu, dl, j);
            float sv = g_ad[d];
            const float* r = h + d * 96;
            float x0 = r[lane], x1 = r[lane + 32], x2 = r[lane + 64];
            float w = edge_w(asi + sv);
            rs += w;
            a0 += w * x0;
            a1 += w * x1;
            a2 += w * x2;
        }
        p += m;
    }

    float inv = (rs > 0.f) ? (1.f / rs) : 0.f;
    a0 *= inv; a1 *= inv; a2 *= inv;
    if (do_relu) {
        a0 = fmaxf(a0, 0.f);
        a1 = fmaxf(a1, 0.f);
        a2 = fmaxf(a2, 0.f);
    }
    float* o = out + (size_t)warp * 96;
    o[lane]      = a0;
    o[lane + 32] = a1;
    o[lane + 64] = a2;
}

// ---------------- 7) tail: restore g_cnt = 0 for the next call --------------
__global__ void tail_zero_kernel(int n) {
    int i = blockIdx.x * blockDim.x + threadIdx.x;
    if (i < n) g_cnt[i] = 0;
}

// ---------------- launch ----------------------------------------------------
extern "C" void kernel_launch(void* const* d_in, const int* in_sizes, int n_in,
                              void* d_out, int out_size)
{
    const void*  eidx = d_in[0];
    const float* x    = (const float*)d_in[1];
    const float* W1   = (const float*)d_in[2];
    const float* a1   = (const float*)d_in[3];
    const float* W2   = (const float*)d_in[4];
    const float* a2   = (const float*)d_in[5];
    float* out = (float*)d_out;

    int E = in_sizes[0] / 2;
    int N = in_sizes[1] / DD;
    if (E > EMAX) E = EMAX;
    if (N > NMAX) N = NMAX;

    int gemm_blocks = (N + 63) / 64;
    int fill_blocks = (E + 255) / 256;
    int warp_blocks = (N + 7) / 8;    // 8 warps (256 threads) per block

    // The ncu single-launch capture window lands on launch #4 -> gather L1.
    convert_count_kernel<<<(E + 255) / 256, 256>>>(eidx, E);              // 1
    rowptr_kernel<<<1, 1024>>>(N);                                        // 2
    mega_gemm_fill_kernel<<<gemm_blocks + fill_blocks, 256>>>(            // 3
        x, W1, a1, g_h, N, E, gemm_blocks);
    gather_kernel<<<warp_blocks, 256>>>(g_h, g_y1, N, 0);                 // 4 <- captured
    mega_gemm_fill_kernel<<<gemm_blocks, 256>>>(                          // 5 (gemm only)
        g_y1, W2, a2, g_h, N, 0, gemm_blocks);
    gather_kernel<<<warp_blocks, 256>>>(g_h, out, N, 1);                  // 6
    tail_zero_kernel<<<(N + 255) / 256, 256>>>(N);                        // 7
}

// round 17
// speedup vs baseline: 5.2537x; 5.2537x over previous
#include <cuda_runtime.h>
#include <cstdint>

// Problem constants (fixed by the dataset)
#define NMAX 100000
#define EMAX 800000
#define DD   96

// ---------------- device scratch (no runtime allocation allowed) -------------
// NOTE: on this GB300 stack, module globals appear to be served from C2C/system
// memory (L2-bypassed, ~200GB/s). Strategy: only sequential/streamed or small
// traffic goes here; all random/high-reuse traffic goes through d_out (HBM).
// g_cnt is zero at module load and re-zeroed by the tail kernel each call.
__device__ int   g_cnt[NMAX];
__device__ int   g_src[EMAX];
__device__ int   g_dst[EMAX];
__device__ int   g_pos[EMAX];            // slot of edge within its src row
__device__ int   g_rowptr[NMAX + 1];
__device__ int   g_dst_sorted[EMAX];
__device__ float g_y1[NMAX * DD];        // layer-1 output / final staging
__device__ float g_as[NMAX];
__device__ float g_ad[NMAX];

// ---------------- 1) convert + count (per-block dtype detect) ---------------
// src begins with arange(N): int32 view of int64 data = [0,0,1,0,2,0,...]
__global__ void convert_count_kernel(const void* __restrict__ eidx, int E) {
    __shared__ int s_flag;
    const int* p32 = (const int*)eidx;
    if (threadIdx.x == 0) {
        s_flag = ((p32[1] | p32[3] | p32[5] | p32[7] | p32[9]) == 0) ? 1 : 0;
    }
    __syncthreads();
    int e = blockIdx.x * blockDim.x + threadIdx.x;
    if (e >= E) return;
    int s, d;
    if (s_flag) {
        const long long* q = (const long long*)eidx;
        s = (int)q[e];
        d = (int)q[E + e];
    } else {
        s = p32[e];
        d = p32[E + e];
    }
    g_src[e] = s;
    g_dst[e] = d;
    g_pos[e] = atomicAdd(&g_cnt[s], 1);
}

// ---------------- 2) rowptr: single-block exclusive scan of counts ----------
__global__ void __launch_bounds__(1024) rowptr_kernel(int n) {
    __shared__ int s_w[32];
    __shared__ int s_tot;
    int t = threadIdx.x;
    int lane = t & 31;
    int wid = t >> 5;
    int carry = 0;

    for (int chunk = 0; chunk < n; chunk += 1024) {
        int i = chunk + t;
        int v = (i < n) ? g_cnt[i] : 0;
        int x = v;
#pragma unroll
        for (int off = 1; off < 32; off <<= 1) {
            int y = __shfl_up_sync(0xffffffffu, x, off);
            if (lane >= off) x += y;
        }
        if (lane == 31) s_w[wid] = x;
        __syncthreads();
        if (t < 32) {
            int wv = s_w[t];
            int win = wv;
#pragma unroll
            for (int off = 1; off < 32; off <<= 1) {
                int y = __shfl_up_sync(0xffffffffu, win, off);
                if (t >= off) win += y;
            }
            if (t == 31) s_tot = win;
            s_w[t] = win - wv;         // exclusive warp offset
        }
        __syncthreads();
        int excl = carry + s_w[wid] + (x - v);
        if (i < n) g_rowptr[i] = excl;
        carry += s_tot;
        __syncthreads();
    }
    if (t == 0) g_rowptr[n] = carry;
}

// ---------------- 3) fill CSR adjacency (atomic-free) -----------------------
__global__ void fill_kernel(int E) {
    int e = blockIdx.x * blockDim.x + threadIdx.x;
    if (e >= E) return;
    int s = g_src[e];
    g_dst_sorted[g_rowptr[s] + g_pos[e]] = g_dst[e];
}

// ---------------- 4/6) GEMM + fused attention dots --------------------------
// H[n,96] = X[n,96] @ W[96,96]; also as[i]=H[i].a[0:96], ad[i]=H[i].a[96:192].
// H is d_out (HBM). BM=64 rows/block, 256 threads, 4 rows x 6 cols each.
__global__ void __launch_bounds__(256) gemm_dots_kernel(
    const float* __restrict__ X, const float* __restrict__ W,
    const float* __restrict__ A, float* __restrict__ H, int n)
{
    __shared__ float Ws[32 * 96];     // [k][j]
    __shared__ float Xs[64 * 33];     // [row][k], padded stride 33

    int tid = threadIdx.x;
    int lane = tid & 31;
    int ct = tid & 15;                // column group: cols [ct*6, ct*6+6)
    int rt = tid >> 4;                // row group: rows rt*4 .. rt*4+3
    int rowBase = blockIdx.x * 64;

    float acc[4][6];
#pragma unroll
    for (int i = 0; i < 4; ++i)
#pragma unroll
        for (int j = 0; j < 6; ++j) acc[i][j] = 0.f;

    for (int kc = 0; kc < 96; kc += 32) {
#pragma unroll
        for (int i = 0; i < 12; ++i) {
            int idx = tid + i * 256;
            Ws[idx] = W[kc * 96 + idx];
        }
#pragma unroll
        for (int i = 0; i < 8; ++i) {
            int idx = tid + i * 256;
            int r = idx >> 5, k = idx & 31;
            int grow = rowBase + r;
            Xs[r * 33 + k] = (grow < n) ? X[grow * 96 + kc + k] : 0.f;
        }
        __syncthreads();

#pragma unroll
        for (int k = 0; k < 32; ++k) {
            float xr[4];
#pragma unroll
            for (int i = 0; i < 4; ++i) xr[i] = Xs[(rt * 4 + i) * 33 + k];
            const float2* wp = (const float2*)&Ws[k * 96 + ct * 6];
            float2 w01 = wp[0], w23 = wp[1], w45 = wp[2];
            float wr[6] = {w01.x, w01.y, w23.x, w23.y, w45.x, w45.y};
#pragma unroll
            for (int i = 0; i < 4; ++i)
#pragma unroll
                for (int j = 0; j < 6; ++j) acc[i][j] += xr[i] * wr[j];
        }
        __syncthreads();
    }

#pragma unroll
    for (int i = 0; i < 4; ++i) {
        int grow = rowBase + rt * 4 + i;
        if (grow < n) {
#pragma unroll
            for (int j = 0; j < 6; ++j)
                H[grow * 96 + ct * 6 + j] = acc[i][j];
        }
    }

    // fused dots
    float aj[6], bj[6];
#pragma unroll
    for (int j = 0; j < 6; ++j) {
        aj[j] = A[ct * 6 + j];
        bj[j] = A[96 + ct * 6 + j];
    }
#pragma unroll
    for (int i = 0; i < 4; ++i) {
        float s = 0.f, t2 = 0.f;
#pragma unroll
        for (int j = 0; j < 6; ++j) {
            s  += acc[i][j] * aj[j];
            t2 += acc[i][j] * bj[j];
        }
#pragma unroll
        for (int off = 8; off > 0; off >>= 1) {
            s  += __shfl_xor_sync(0xffffffffu, s,  off);
            t2 += __shfl_xor_sync(0xffffffffu, t2, off);
        }
        int grow = rowBase + rt * 4 + i;
        if ((lane & 15) == 0 && grow < n) {
            g_as[grow] = s;
            g_ad[grow] = t2;
        }
    }
}

// ---------------- 5/7) gather -----------------------------------------------
// out[i] = sum_e w_e * h[dst_e] / sum_e w_e ; one warp per node.
// h = d_out (HBM, L2-resident, 8x reuse). out = slow global (sequential).
__device__ __forceinline__ float edge_w(float s) {
    // leaky_relu(s) == fmaxf(s, 0.01*s) for both signs
    return __expf(-fmaxf(s, 0.01f * s));
}

__global__ void __launch_bounds__(256) gather_kernel(
    const float* __restrict__ h, float* __restrict__ out,
    int n, int do_relu)
{
    int warp = (blockIdx.x * blockDim.x + threadIdx.x) >> 5;
    int lane = threadIdx.x & 31;
    if (warp >= n) return;

    int p   = g_rowptr[warp];
    int end = g_rowptr[warp + 1];
    float asi = g_as[warp];

    float a0 = 0.f, a1 = 0.f, a2 = 0.f, rs = 0.f;

    while (p < end) {
        int m = end - p;
        if (m > 32) m = 32;
        int dl = (lane < m) ? g_dst_sorted[p + lane] : 0;

        int j = 0;
        for (; j + 4 <= m; j += 4) {
            int d0 = __shfl_sync(0xffffffffu, dl, j);
            int d1 = __shfl_sync(0xffffffffu, dl, j + 1);
            int d2 = __shfl_sync(0xffffffffu, dl, j + 2);
            int d3 = __shfl_sync(0xffffffffu, dl, j + 3);
            float s0 = g_ad[d0], s1 = g_ad[d1], s2 = g_ad[d2], s3 = g_ad[d3];
            const float* r0 = h + d0 * 96;
            const float* r1 = h + d1 * 96;
            const float* r2 = h + d2 * 96;
            const float* r3 = h + d3 * 96;
            float x00 = r0[lane], x01 = r0[lane + 32], x02 = r0[lane + 64];
            float x10 = r1[lane], x11 = r1[lane + 32], x12 = r1[lane + 64];
            float x20 = r2[lane], x21 = r2[lane + 32], x22 = r2[lane + 64];
            float x30 = r3[lane], x31 = r3[lane + 32], x32 = r3[lane + 64];
            float w0 = edge_w(asi + s0);
            float w1 = edge_w(asi + s1);
            float w2 = edge_w(asi + s2);
            float w3 = edge_w(asi + s3);
            rs += (w0 + w1) + (w2 + w3);
            a0 += w0 * x00 + w1 * x10 + w2 * x20 + w3 * x30;
            a1 += w0 * x01 + w1 * x11 + w2 * x21 + w3 * x31;
            a2 += w0 * x02 + w1 * x12 + w2 * x22 + w3 * x32;
        }
        for (; j < m; ++j) {
            int d = __shfl_sync(0xffffffffu, dl, j);
            float sv = g_ad[d];
            const float* r = h + d * 96;
            float x0 = r[lane], x1 = r[lane + 32], x2 = r[lane + 64];
            float w = edge_w(asi + sv);
            rs += w;
            a0 += w * x0;
            a1 += w * x1;
            a2 += w * x2;
        }
        p += m;
    }

    float inv = (rs > 0.f) ? (1.f / rs) : 0.f;
    a0 *= inv; a1 *= inv; a2 *= inv;
    if (do_relu) {
        a0 = fmaxf(a0, 0.f);
        a1 = fmaxf(a1, 0.f);
        a2 = fmaxf(a2, 0.f);
    }
    float* o = out + (size_t)warp * 96;
    o[lane]      = a0;
    o[lane + 32] = a1;
    o[lane + 64] = a2;
}

// ---------------- 8) copy staged result -> d_out (float4, streamed) ---------
__global__ void copy_out_kernel(const float4* __restrict__ src,
                                float4* __restrict__ dst, int n4)
{
    int i = blockIdx.x * blockDim.x + threadIdx.x;
    if (i < n4) dst[i] = src[i];
}

// ---------------- 9) tail: restore g_cnt = 0 for the next call --------------
__global__ void tail_zero_kernel(int n) {
    int i = blockIdx.x * blockDim.x + threadIdx.x;
    if (i < n) g_cnt[i] = 0;
}

// ---------------- launch ----------------------------------------------------
extern "C" void kernel_launch(void* const* d_in, const int* in_sizes, int n_in,
                              void* d_out, int out_size)
{
    const void*  eidx = d_in[0];
    const float* x    = (const float*)d_in[1];
    const float* W1   = (const float*)d_in[2];
    const float* a1   = (const float*)d_in[3];
    const float* W2   = (const float*)d_in[4];
    const float* a2   = (const float*)d_in[5];
    float* out = (float*)d_out;

    int E = in_sizes[0] / 2;
    int N = in_sizes[1] / DD;
    if (E > EMAX) E = EMAX;
    if (N > NMAX) N = NMAX;

    int gemm_blocks = (N + 63) / 64;
    int warp_blocks = (N + 7) / 8;    // 8 warps (256 threads) per block
    int n4 = (N * DD) / 4;            // DD=96 -> divisible by 4

    convert_count_kernel<<<(E + 255) / 256, 256>>>(eidx, E);              // 1
    rowptr_kernel<<<1, 1024>>>(N);                                        // 2
    fill_kernel<<<(E + 255) / 256, 256>>>(E);                             // 3
    // layer 1: h1 lives in d_out (HBM) for fast random gather reads
    gemm_dots_kernel<<<gemm_blocks, 256>>>(x, W1, a1, out, N);            // 4
    gather_kernel<<<warp_blocks, 256>>>(out, g_y1, N, 0);                 // 5
    // layer 2: h2 lives in d_out; result staged to g_y1 (y1 dead after gemm2)
    gemm_dots_kernel<<<gemm_blocks, 256>>>(g_y1, W2, a2, out, N);         // 6
    gather_kernel<<<warp_blocks, 256>>>(out, g_y1, N, 1);                 // 7
    copy_out_kernel<<<(n4 + 255) / 256, 256>>>(                           // 8
        (const float4*)g_y1, (float4*)out, n4);
    tail_zero_kernel<<<(N + 255) / 256, 256>>>(N);                        // 9
}